// round 2
// baseline (speedup 1.0000x reference)
#include <cuda_runtime.h>

// DynamicRouting fused kernel:
//   con[b,g,fo,p] = sum_fi W[g,fo,fi] * x[b,g,fi,p]     (grouped 1x1 conv)
//   3-iter routing over `con` kept entirely in SMEM, output (B,FO,H,W) fp32.

namespace {
constexpr int Gn      = 8;
constexpr int FIn     = 64;
constexpr int FOn     = 64;
constexpr int HWn     = 4096;   // H*W
constexpr int Bn      = 16;
constexpr int PX      = 32;     // pixels per CTA
constexpr int THREADS = 128;

constexpr int SW_STRIDE = 65;   // sW[fo][fi], padded (conflict-free broadcast reads)
constexpr int SX_STRIDE = 36;   // sX[fi][px], padded, 16B-aligned rows
constexpr int SC_STRIDE = 36;   // sC[(g*FO+fo)][px], padded, 16B-aligned rows

constexpr int OFF_W = 0;
constexpr int OFF_X = OFF_W + FOn * SW_STRIDE;            // 4160
constexpr int OFF_C = OFF_X + FIn * SX_STRIDE;            // +2304
constexpr int OFF_V = OFF_C + Gn * FOn * SC_STRIDE;       // +18432
constexpr int OFF_B = OFF_V + FOn * PX;                   // +2048
constexpr int OFF_A = OFF_B + Gn * PX;                    // +256
constexpr int SMEM_FLOATS = OFF_A + Gn * PX;              // +256
constexpr int SMEM_BYTES  = SMEM_FLOATS * 4;              // 109,824 B
}

__global__ void __launch_bounds__(THREADS, 2)
dynrout_kernel(const float* __restrict__ x,
               const float* __restrict__ w,
               const float* __restrict__ bias,
               float* __restrict__ out)
{
    extern __shared__ float sm[];
    float* sW = sm + OFF_W;
    float* sX = sm + OFF_X;
    float* sC = sm + OFF_C;
    float* sV = sm + OFF_V;
    float* sB = sm + OFF_B;
    float* sA = sm + OFF_A;

    const int t    = threadIdx.x;
    const int tile = blockIdx.x;
    const int bi   = tile >> 7;           // 4096/32 = 128 tiles per batch image
    const int p0   = (tile & 127) * PX;

    // ---------------- prefetch registers (double-buffer gmem loads) ----------
    float4 rx[4];   // x tile:  64 fi x 32 px = 512 float4 / 128 thr = 4 each
    float4 rw[8];   // W_g:     64 fo x 64 fi = 1024 float4 / 128 thr = 8 each

    auto load_group = [&](int g) {
        const float* xb = x + ((size_t)(bi * (Gn * FIn) + g * FIn)) * HWn + p0;
        #pragma unroll
        for (int k = 0; k < 4; k++) {
            int idx = t + k * THREADS;          // 0..511
            int fi  = idx >> 3;
            int px4 = idx & 7;
            rx[k] = *reinterpret_cast<const float4*>(xb + (size_t)fi * HWn + px4 * 4);
        }
        const float* wb = w + (size_t)g * FOn * FIn;
        #pragma unroll
        for (int k = 0; k < 8; k++) {
            int idx = t + k * THREADS;          // 0..1023
            int fo  = idx >> 4;
            int fi4 = idx & 15;
            rw[k] = *reinterpret_cast<const float4*>(wb + fo * FIn + fi4 * 4);
        }
    };

    auto store_group = [&]() {
        #pragma unroll
        for (int k = 0; k < 4; k++) {
            int idx = t + k * THREADS;
            int fi  = idx >> 3;
            int px4 = idx & 7;
            *reinterpret_cast<float4*>(sX + fi * SX_STRIDE + px4 * 4) = rx[k];
        }
        #pragma unroll
        for (int k = 0; k < 8; k++) {
            int idx = t + k * THREADS;
            int fo  = idx >> 4;
            int fi4 = idx & 15;
            float* d = sW + fo * SW_STRIDE + fi4 * 4;
            d[0] = rw[k].x; d[1] = rw[k].y; d[2] = rw[k].z; d[3] = rw[k].w;
        }
    };

    // ---------------- GEMM: con = W_g @ X_g per group -------------------------
    const int fo0 = (t >> 3) * 4;   // 16 fo blocks
    const int px0 = (t & 7) * 4;    // 8 px blocks

    load_group(0);
    for (int g = 0; g < Gn; g++) {
        __syncthreads();            // previous group's SMEM reads finished
        store_group();
        __syncthreads();
        if (g + 1 < Gn) load_group(g + 1);   // overlap next gmem fetch with compute

        float acc[4][4];
        #pragma unroll
        for (int i = 0; i < 4; i++)
            #pragma unroll
            for (int j = 0; j < 4; j++) acc[i][j] = 0.f;

        #pragma unroll 8
        for (int fi = 0; fi < FIn; fi++) {
            float4 xv = *reinterpret_cast<const float4*>(sX + fi * SX_STRIDE + px0);
            float w0 = sW[(fo0 + 0) * SW_STRIDE + fi];
            float w1 = sW[(fo0 + 1) * SW_STRIDE + fi];
            float w2 = sW[(fo0 + 2) * SW_STRIDE + fi];
            float w3 = sW[(fo0 + 3) * SW_STRIDE + fi];
            acc[0][0] += w0 * xv.x; acc[0][1] += w0 * xv.y; acc[0][2] += w0 * xv.z; acc[0][3] += w0 * xv.w;
            acc[1][0] += w1 * xv.x; acc[1][1] += w1 * xv.y; acc[1][2] += w1 * xv.z; acc[1][3] += w1 * xv.w;
            acc[2][0] += w2 * xv.x; acc[2][1] += w2 * xv.y; acc[2][2] += w2 * xv.z; acc[2][3] += w2 * xv.w;
            acc[3][0] += w3 * xv.x; acc[3][1] += w3 * xv.y; acc[3][2] += w3 * xv.z; acc[3][3] += w3 * xv.w;
        }

        float* c = sC + ((size_t)g * FOn + fo0) * SC_STRIDE + px0;
        #pragma unroll
        for (int i = 0; i < 4; i++) {
            *reinterpret_cast<float4*>(c + i * SC_STRIDE) =
                make_float4(acc[i][0], acc[i][1], acc[i][2], acc[i][3]);
        }
    }
    __syncthreads();

    // ---------------- routing (3 iterations, all in SMEM) ---------------------
    const int px = t & 31;          // fixed pixel lane for this thread
    const int ga = t >> 5;          // phase-B groups: ga and ga+4
    const int gb = ga + 4;

    // iter 0, phase A: alpha = sigmoid(0) = 0.5
    #pragma unroll
    for (int k = 0; k < 16; k++) {
        int fo = (t >> 5) + k * 4;
        float s = 0.f;
        #pragma unroll
        for (int g = 0; g < Gn; g++) s += sC[(g * FOn + fo) * SC_STRIDE + px];
        sV[fo * PX + px] = 0.5f * s;
    }
    __syncthreads();

    // phase B: beta[g,px] (+)= sum_fo v[fo,px]*con[g,fo,px]; alpha = sigmoid(beta)
    auto phaseB = [&](bool first) {
        float d0 = 0.f, d1 = 0.f;
        #pragma unroll 8
        for (int fo = 0; fo < FOn; fo++) {
            float vv = sV[fo * PX + px];
            d0 += vv * sC[(ga * FOn + fo) * SC_STRIDE + px];
            d1 += vv * sC[(gb * FOn + fo) * SC_STRIDE + px];
        }
        float b0 = first ? d0 : (sB[ga * PX + px] + d0);
        float b1 = first ? d1 : (sB[gb * PX + px] + d1);
        sB[ga * PX + px] = b0;
        sB[gb * PX + px] = b1;
        sA[ga * PX + px] = 1.f / (1.f + __expf(-b0));
        sA[gb * PX + px] = 1.f / (1.f + __expf(-b1));
    };

    phaseB(true);
    __syncthreads();

    // iter 1, phase A with alpha from SMEM
    {
        float al[Gn];
        #pragma unroll
        for (int g = 0; g < Gn; g++) al[g] = sA[g * PX + px];
        #pragma unroll
        for (int k = 0; k < 16; k++) {
            int fo = (t >> 5) + k * 4;
            float s = 0.f;
            #pragma unroll
            for (int g = 0; g < Gn; g++) s += al[g] * sC[(g * FOn + fo) * SC_STRIDE + px];
            sV[fo * PX + px] = s;
        }
    }
    __syncthreads();

    phaseB(false);
    __syncthreads();

    // iter 2 (final): out[b,fo,p] = sum_g alpha[g]*con[g,fo,p] + bias[fo]
    {
        float al[Gn];
        #pragma unroll
        for (int g = 0; g < Gn; g++) al[g] = sA[g * PX + px];
        float* ob = out + (size_t)bi * FOn * HWn + p0;
        #pragma unroll
        for (int k = 0; k < 16; k++) {
            int fo = (t >> 5) + k * 4;
            float s = 0.f;
            #pragma unroll
            for (int g = 0; g < Gn; g++) s += al[g] * sC[(g * FOn + fo) * SC_STRIDE + px];
            ob[(size_t)fo * HWn + px] = s + __ldg(&bias[fo]);
        }
    }
}

extern "C" void kernel_launch(void* const* d_in, const int* in_sizes, int n_in,
                              void* d_out, int out_size)
{
    // Map inputs by element count (robust to ordering): x=33554432, w=32768, bias=64
    const float* x = nullptr;
    const float* w = nullptr;
    const float* b = nullptr;
    for (int i = 0; i < n_in; i++) {
        if (in_sizes[i] == Bn * Gn * FIn * HWn)      x = (const float*)d_in[i];
        else if (in_sizes[i] == Gn * FOn * FIn)      w = (const float*)d_in[i];
        else if (in_sizes[i] == FOn)                 b = (const float*)d_in[i];
    }
    float* out = (float*)d_out;

    static bool attr_set = false;
    if (!attr_set) {
        cudaFuncSetAttribute(dynrout_kernel,
                             cudaFuncAttributeMaxDynamicSharedMemorySize, SMEM_BYTES);
        attr_set = true;
    }

    const int n_tiles = (Bn * HWn) / PX;   // 2048
    dynrout_kernel<<<n_tiles, THREADS, SMEM_BYTES>>>(x, w, b, out);
}

// round 3
// speedup vs baseline: 1.0252x; 1.0252x over previous
#include <cuda_runtime.h>
#include <cstdint>

// DynamicRouting fused kernel (R2: packed f32x2 math):
//   con[b,g,fo,p] = sum_fi W[g,fo,fi] * x[b,g,fi,p]     (grouped 1x1 conv)
//   3-iter routing over `con` kept entirely in SMEM, output (B,FO,H,W) fp32.

namespace {
constexpr int Gn      = 8;
constexpr int FIn     = 64;
constexpr int FOn     = 64;
constexpr int HWn     = 4096;   // H*W
constexpr int Bn      = 16;
constexpr int PX      = 32;     // pixels per CTA
constexpr int THREADS = 128;

constexpr int SW_STRIDE = 65;   // sW[fo][fi], padded (conflict-free broadcast reads)
constexpr int SX_STRIDE = 36;   // sX[fi][px], padded, 16B-aligned rows
constexpr int SC_STRIDE = 36;   // sC[(g*FO+fo)][px], padded, 16B-aligned rows

constexpr int OFF_W = 0;
constexpr int OFF_X = OFF_W + FOn * SW_STRIDE;            // 4160
constexpr int OFF_C = OFF_X + FIn * SX_STRIDE;            // +2304
constexpr int OFF_V = OFF_C + Gn * FOn * SC_STRIDE;       // +18432
constexpr int OFF_B = OFF_V + FOn * PX;                   // +2048
constexpr int OFF_A = OFF_B + Gn * PX;                    // +256
constexpr int SMEM_FLOATS = OFF_A + Gn * PX;              // +256
constexpr int SMEM_BYTES  = SMEM_FLOATS * 4;              // 109,824 B
}

// ---- packed f32x2 helpers (sm_103a) ---------------------------------------
__device__ __forceinline__ uint64_t f2_pack(float lo, float hi) {
    uint64_t r;
    asm("mov.b64 %0, {%1, %2};" : "=l"(r) : "f"(lo), "f"(hi));
    return r;
}
__device__ __forceinline__ void f2_unpack(uint64_t v, float& lo, float& hi) {
    asm("mov.b64 {%0, %1}, %2;" : "=f"(lo), "=f"(hi) : "l"(v));
}
__device__ __forceinline__ uint64_t f2_fma(uint64_t a, uint64_t b, uint64_t c) {
    uint64_t d;
    asm("fma.rn.f32x2 %0, %1, %2, %3;" : "=l"(d) : "l"(a), "l"(b), "l"(c));
    return d;
}
__device__ __forceinline__ uint64_t f2_add(uint64_t a, uint64_t b) {
    uint64_t d;
    asm("add.rn.f32x2 %0, %1, %2;" : "=l"(d) : "l"(a), "l"(b));
    return d;
}

__global__ void __launch_bounds__(THREADS, 2)
dynrout_kernel(const float* __restrict__ x,
               const float* __restrict__ w,
               const float* __restrict__ bias,
               float* __restrict__ out)
{
    extern __shared__ float sm[];
    float* sW = sm + OFF_W;
    float* sX = sm + OFF_X;
    float* sC = sm + OFF_C;
    float* sV = sm + OFF_V;
    float* sB = sm + OFF_B;
    float* sA = sm + OFF_A;

    const int t    = threadIdx.x;
    const int tile = blockIdx.x;
    const int bi   = tile >> 7;           // 4096/32 = 128 tiles per batch image
    const int p0   = (tile & 127) * PX;

    // ---------------- prefetch registers (double-buffer gmem loads) ----------
    float4 rx[4];   // x tile:  64 fi x 32 px = 512 float4 / 128 thr = 4 each
    float4 rw[8];   // W_g:     64 fo x 64 fi = 1024 float4 / 128 thr = 8 each

    auto load_group = [&](int g) {
        const float* xb = x + ((size_t)(bi * (Gn * FIn) + g * FIn)) * HWn + p0;
        #pragma unroll
        for (int k = 0; k < 4; k++) {
            int idx = t + k * THREADS;          // 0..511
            int fi  = idx >> 3;
            int px4 = idx & 7;
            rx[k] = *reinterpret_cast<const float4*>(xb + (size_t)fi * HWn + px4 * 4);
        }
        const float* wb = w + (size_t)g * FOn * FIn;
        #pragma unroll
        for (int k = 0; k < 8; k++) {
            int idx = t + k * THREADS;          // 0..1023
            int fo  = idx >> 4;
            int fi4 = idx & 15;
            rw[k] = *reinterpret_cast<const float4*>(wb + fo * FIn + fi4 * 4);
        }
    };

    auto store_group = [&]() {
        #pragma unroll
        for (int k = 0; k < 4; k++) {
            int idx = t + k * THREADS;
            int fi  = idx >> 3;
            int px4 = idx & 7;
            *reinterpret_cast<float4*>(sX + fi * SX_STRIDE + px4 * 4) = rx[k];
        }
        #pragma unroll
        for (int k = 0; k < 8; k++) {
            int idx = t + k * THREADS;
            int fo  = idx >> 4;
            int fi4 = idx & 15;
            float* d = sW + fo * SW_STRIDE + fi4 * 4;
            d[0] = rw[k].x; d[1] = rw[k].y; d[2] = rw[k].z; d[3] = rw[k].w;
        }
    };

    // ---------------- GEMM: con = W_g @ X_g per group (packed f32x2) ---------
    const int fo0 = (t >> 3) * 4;   // 16 fo blocks
    const int px0 = (t & 7) * 4;    // 8 px blocks

    load_group(0);
    for (int g = 0; g < Gn; g++) {
        __syncthreads();            // previous group's SMEM reads finished
        store_group();
        __syncthreads();
        if (g + 1 < Gn) load_group(g + 1);   // overlap next gmem fetch with compute

        uint64_t acc[4][2];         // 4 fo x (2 px-pairs)
        #pragma unroll
        for (int i = 0; i < 4; i++) { acc[i][0] = 0ull; acc[i][1] = 0ull; }

        #pragma unroll 8
        for (int fi = 0; fi < FIn; fi++) {
            const uint64_t* xv =
                reinterpret_cast<const uint64_t*>(sX + fi * SX_STRIDE + px0);
            uint64_t x01 = xv[0];
            uint64_t x23 = xv[1];
            #pragma unroll
            for (int i = 0; i < 4; i++) {
                float wv = sW[(fo0 + i) * SW_STRIDE + fi];
                uint64_t wp = f2_pack(wv, wv);
                acc[i][0] = f2_fma(wp, x01, acc[i][0]);
                acc[i][1] = f2_fma(wp, x23, acc[i][1]);
            }
        }

        float* c = sC + ((size_t)g * FOn + fo0) * SC_STRIDE + px0;
        #pragma unroll
        for (int i = 0; i < 4; i++) {
            uint64_t* cr = reinterpret_cast<uint64_t*>(c + i * SC_STRIDE);
            cr[0] = acc[i][0];
            cr[1] = acc[i][1];
        }
    }
    __syncthreads();

    // ---------------- routing (3 iterations, all in SMEM, packed px-pairs) ---
    const int pp  = t & 15;         // pixel-pair index (px = 2*pp, 2*pp+1)
    const int sl  = t >> 4;         // slice 0..7
    const int pb  = pp * 2;         // base pixel of the pair

    // iter 0, phase A: alpha = sigmoid(0) = 0.5
    {
        const uint64_t half2 = f2_pack(0.5f, 0.5f);
        #pragma unroll
        for (int k = 0; k < 8; k++) {
            int fo = sl + k * 8;
            uint64_t s = 0ull;
            #pragma unroll
            for (int g = 0; g < Gn; g++) {
                uint64_t c2 = *reinterpret_cast<const uint64_t*>(
                    sC + (g * FOn + fo) * SC_STRIDE + pb);
                s = f2_add(s, c2);
            }
            // v = 0.5 * s  (fma with zero addend)
            *reinterpret_cast<uint64_t*>(sV + fo * PX + pb) = f2_fma(half2, s, 0ull);
        }
    }
    __syncthreads();

    // phase B: beta[g,px] (+)= sum_fo v[fo,px]*con[g,fo,px]; alpha = sigmoid(beta)
    // thread handles group g = sl, pixel pair pp
    auto phaseB = [&](bool first) {
        const int g = sl;
        uint64_t d = 0ull;
        #pragma unroll 8
        for (int fo = 0; fo < FOn; fo++) {
            uint64_t v2 = *reinterpret_cast<const uint64_t*>(sV + fo * PX + pb);
            uint64_t c2 = *reinterpret_cast<const uint64_t*>(
                sC + (g * FOn + fo) * SC_STRIDE + pb);
            d = f2_fma(v2, c2, d);
        }
        float dlo, dhi;
        f2_unpack(d, dlo, dhi);
        float b0 = first ? dlo : (sB[g * PX + pb + 0] + dlo);
        float b1 = first ? dhi : (sB[g * PX + pb + 1] + dhi);
        sB[g * PX + pb + 0] = b0;
        sB[g * PX + pb + 1] = b1;
        sA[g * PX + pb + 0] = 1.f / (1.f + __expf(-b0));
        sA[g * PX + pb + 1] = 1.f / (1.f + __expf(-b1));
    };

    phaseB(true);
    __syncthreads();

    // iter 1, phase A with alpha from SMEM
    {
        uint64_t al[Gn];
        #pragma unroll
        for (int g = 0; g < Gn; g++)
            al[g] = *reinterpret_cast<const uint64_t*>(sA + g * PX + pb);
        #pragma unroll
        for (int k = 0; k < 8; k++) {
            int fo = sl + k * 8;
            uint64_t s = 0ull;
            #pragma unroll
            for (int g = 0; g < Gn; g++) {
                uint64_t c2 = *reinterpret_cast<const uint64_t*>(
                    sC + (g * FOn + fo) * SC_STRIDE + pb);
                s = f2_fma(al[g], c2, s);
            }
            *reinterpret_cast<uint64_t*>(sV + fo * PX + pb) = s;
        }
    }
    __syncthreads();

    phaseB(false);
    __syncthreads();

    // iter 2 (final): out[b,fo,p] = sum_g alpha[g]*con[g,fo,p] + bias[fo]
    {
        uint64_t al[Gn];
        #pragma unroll
        for (int g = 0; g < Gn; g++)
            al[g] = *reinterpret_cast<const uint64_t*>(sA + g * PX + pb);
        float* ob = out + (size_t)bi * FOn * HWn + p0;
        #pragma unroll
        for (int k = 0; k < 8; k++) {
            int fo = sl + k * 8;
            uint64_t s = 0ull;
            #pragma unroll
            for (int g = 0; g < Gn; g++) {
                uint64_t c2 = *reinterpret_cast<const uint64_t*>(
                    sC + (g * FOn + fo) * SC_STRIDE + pb);
                s = f2_fma(al[g], c2, s);
            }
            float slo, shi;
            f2_unpack(s, slo, shi);
            float bv = __ldg(&bias[fo]);
            float2 o2 = make_float2(slo + bv, shi + bv);
            *reinterpret_cast<float2*>(ob + (size_t)fo * HWn + pb) = o2;
        }
    }
}

extern "C" void kernel_launch(void* const* d_in, const int* in_sizes, int n_in,
                              void* d_out, int out_size)
{
    // Map inputs by element count (robust to ordering): x=33554432, w=32768, bias=64
    const float* x = nullptr;
    const float* w = nullptr;
    const float* b = nullptr;
    for (int i = 0; i < n_in; i++) {
        if (in_sizes[i] == Bn * Gn * FIn * HWn)      x = (const float*)d_in[i];
        else if (in_sizes[i] == Gn * FOn * FIn)      w = (const float*)d_in[i];
        else if (in_sizes[i] == FOn)                 b = (const float*)d_in[i];
    }
    float* out = (float*)d_out;

    static bool attr_set = false;
    if (!attr_set) {
        cudaFuncSetAttribute(dynrout_kernel,
                             cudaFuncAttributeMaxDynamicSharedMemorySize, SMEM_BYTES);
        attr_set = true;
    }

    const int n_tiles = (Bn * HWn) / PX;   // 2048
    dynrout_kernel<<<n_tiles, THREADS, SMEM_BYTES>>>(x, w, b, out);
}

// round 5
// speedup vs baseline: 1.7082x; 1.6663x over previous
#include <cuda_runtime.h>
#include <cstdint>

// DynamicRouting (R4): mma.sync tf32 tensor-core GEMM (sm_80 PTX — compiles for
// compute_103 without the 'a' feature set) + Gram-matrix routing.
//   con[g,fo,px] = sum_fi W[g,fo,fi] * x[b,g,fi,px]   -> SMEM fp32
//   Gram[g,g',px] = sum_fo con_g * con_g'             -> one SMEM pass
//   routing (3 iters) on 8x8 Gram in registers; final alpha-combine pass.

namespace {
constexpr int Gn   = 8;
constexpr int FIn  = 64;
constexpr int FOn  = 64;
constexpr int HWn  = 4096;
constexpr int Bn   = 16;
constexpr int PXT  = 64;            // pixels per CTA
constexpr int THREADS = 256;        // 8 warps

// SMEM strides (in 32-bit words) chosen for conflict-free fragment access
constexpr int SXs = 72;             // X [fi][px]  : bank = (8*fi + px) % 32
constexpr int SWs = 68;             // W [fo][fi]  : bank = (4*fo + fi) % 32
constexpr int SCs = 65;             // con [g*64+fo][px]

// SMEM word offsets
constexpr int CONo = 0;                         // 512*65      = 33280 words
constexpr int X0o  = CONo + Gn * FOn * SCs;     // 33280
constexpr int X1o  = X0o + FIn * SXs;           // +4608
constexpr int W0o  = X1o + FIn * SXs;           // +4608
constexpr int W1o  = W0o + FOn * SWs;           // +4352
constexpr int ALPo = W1o + FOn * SWs;           // +4352 -> 51200
constexpr int SMEM_WORDS = ALPo + Gn * PXT;     // +512  -> 51712
constexpr int SMEM_BYTES = SMEM_WORDS * 4;      // 206848 B
}

// ---------------- helpers ----------------------------------------------------
__device__ __forceinline__ uint32_t cvt_tf32(float f) {
    uint32_t r;
    asm("cvt.rna.tf32.f32 %0, %1;" : "=r"(r) : "f"(f));
    return r;
}

__device__ __forceinline__ void mma_tf32(float c[4],
                                         uint32_t a0, uint32_t a1,
                                         uint32_t a2, uint32_t a3,
                                         uint32_t b0, uint32_t b1) {
    asm volatile(
        "mma.sync.aligned.m16n8k8.row.col.f32.tf32.tf32.f32 "
        "{%0,%1,%2,%3}, {%4,%5,%6,%7}, {%8,%9}, {%0,%1,%2,%3};"
        : "+f"(c[0]), "+f"(c[1]), "+f"(c[2]), "+f"(c[3])
        : "r"(a0), "r"(a1), "r"(a2), "r"(a3), "r"(b0), "r"(b1));
}

__device__ __forceinline__ float sigmoidf_(float v) {
    return 1.f / (1.f + __expf(-v));
}

// triangular pair index for symmetric 8x8 Gram, a<=b
__device__ __forceinline__ int pidx(int a, int b) {
    int lo = a < b ? a : b, hi = a < b ? b : a;
    return lo * 8 - lo * (lo - 1) / 2 + (hi - lo);
}

// ---------------- kernel ------------------------------------------------------
__global__ void __launch_bounds__(THREADS, 1)
dynrout_mma_kernel(const float* __restrict__ x,
                   const float* __restrict__ w,
                   const float* __restrict__ bias,
                   float* __restrict__ out)
{
    extern __shared__ uint32_t smu[];
    float* smf = reinterpret_cast<float*>(smu);

    const int t    = threadIdx.x;
    const int wid  = t >> 5;
    const int lane = t & 31;
    const int gid  = lane >> 2;     // group-of-4 id (0..7)
    const int tid4 = lane & 3;      // id within quad

    const int cta = blockIdx.x;
    const int bi  = cta >> 6;       // 64 px-tiles per image
    const int p0  = (cta & 63) * PXT;

    // warp tile: 16 px x 32 fo
    const int pxb = (wid & 3) * 16;         // px quarter
    const int fob = (wid >> 2) * 32;        // fo half

    // ---------------- gmem prefetch registers --------------------------------
    float4 rx[4], rw[4];
    auto load_regs = [&](int g) {
        const float* xg = x + ((size_t)bi * (Gn * FIn) + g * FIn) * HWn + p0;
        const float* wg = w + (size_t)g * FOn * FIn;
        #pragma unroll
        for (int k = 0; k < 4; k++) {
            int q   = t + k * THREADS;      // 0..1023
            int r0  = q >> 4;               // fi (X) / fo (W)
            int c4  = q & 15;               // px4 / fi4
            rx[k] = *reinterpret_cast<const float4*>(xg + (size_t)r0 * HWn + c4 * 4);
            rw[k] = *reinterpret_cast<const float4*>(wg + r0 * FIn + c4 * 4);
        }
    };
    auto store_regs = [&](int buf) {
        const int xo = buf ? X1o : X0o;
        const int wo = buf ? W1o : W0o;
        #pragma unroll
        for (int k = 0; k < 4; k++) {
            int q  = t + k * THREADS;
            int r0 = q >> 4;
            int c4 = q & 15;
            uint4 xv = make_uint4(cvt_tf32(rx[k].x), cvt_tf32(rx[k].y),
                                  cvt_tf32(rx[k].z), cvt_tf32(rx[k].w));
            uint4 wv = make_uint4(cvt_tf32(rw[k].x), cvt_tf32(rw[k].y),
                                  cvt_tf32(rw[k].z), cvt_tf32(rw[k].w));
            *reinterpret_cast<uint4*>(&smu[xo + r0 * SXs + c4 * 4]) = xv;
            *reinterpret_cast<uint4*>(&smu[wo + r0 * SWs + c4 * 4]) = wv;
        }
    };

    // ---------------- GEMM over 8 groups (double-buffered) -------------------
    load_regs(0);
    store_regs(0);
    __syncthreads();

    for (int g = 0; g < Gn; g++) {
        if (g + 1 < Gn) load_regs(g + 1);   // gmem -> regs, overlaps mma

        const int xo = (g & 1) ? X1o : X0o;
        const int wo = (g & 1) ? W1o : W0o;

        float acc[4][4];
        #pragma unroll
        for (int n = 0; n < 4; n++)
            #pragma unroll
            for (int j = 0; j < 4; j++) acc[n][j] = 0.f;

        #pragma unroll
        for (int s = 0; s < 8; s++) {
            const int fi0 = s * 8;
            // A fragment (16 px x 8 k), element-exact loads, conflict-free
            uint32_t a0 = smu[xo + (fi0 + tid4)     * SXs + pxb + gid];
            uint32_t a1 = smu[xo + (fi0 + tid4)     * SXs + pxb + gid + 8];
            uint32_t a2 = smu[xo + (fi0 + 4 + tid4) * SXs + pxb + gid];
            uint32_t a3 = smu[xo + (fi0 + 4 + tid4) * SXs + pxb + gid + 8];
            #pragma unroll
            for (int n = 0; n < 4; n++) {
                int fo = fob + n * 8 + gid;
                uint32_t b0 = smu[wo + fo * SWs + fi0 + tid4];
                uint32_t b1 = smu[wo + fo * SWs + fi0 + 4 + tid4];
                mma_tf32(acc[n], a0, a1, a2, a3, b0, b1);
            }
        }

        // store con[g][fo][px]  (c0:(gid, 2*tid4) c1:+fo c2:(gid+8,..) c3)
        #pragma unroll
        for (int n = 0; n < 4; n++) {
            int fo = fob + n * 8 + 2 * tid4;
            int cbase = CONo + (g * FOn + fo) * SCs;
            smf[cbase           + pxb + gid]     = acc[n][0];
            smf[cbase + SCs     + pxb + gid]     = acc[n][1];
            smf[cbase           + pxb + gid + 8] = acc[n][2];
            smf[cbase + SCs     + pxb + gid + 8] = acc[n][3];
        }

        if (g + 1 < Gn) {
            store_regs((g + 1) & 1);        // safe: that buffer last read at g-1
        }
        __syncthreads();
    }

    // ---------------- Gram pass ----------------------------------------------
    // thread quad per pixel: px = t>>2, foc = t&3 covers 16 fo each
    {
        const int px  = t >> 2;
        const int foc = t & 3;
        float acc[36];
        #pragma unroll
        for (int p = 0; p < 36; p++) acc[p] = 0.f;

        #pragma unroll 4
        for (int i = 0; i < 16; i++) {
            int fo = foc * 16 + i;
            float cg[Gn];
            #pragma unroll
            for (int g = 0; g < Gn; g++)
                cg[g] = smf[CONo + (g * FOn + fo) * SCs + px];
            int p = 0;
            #pragma unroll
            for (int a = 0; a < Gn; a++)
                #pragma unroll
                for (int b = a; b < Gn; b++)
                    acc[p++] += cg[a] * cg[b];
        }
        // reduce across the quad (foc 0..3 are adjacent lanes)
        #pragma unroll
        for (int p = 0; p < 36; p++) {
            acc[p] += __shfl_xor_sync(0xFFFFFFFFu, acc[p], 1);
            acc[p] += __shfl_xor_sync(0xFFFFFFFFu, acc[p], 2);
        }

        // routing on 8x8 Gram (redundant across quad; foc==0 stores)
        float beta[Gn], alpha[Gn];
        #pragma unroll
        for (int g = 0; g < Gn; g++) {
            float s = 0.f;
            #pragma unroll
            for (int g2 = 0; g2 < Gn; g2++) s += acc[pidx(g2, g)];
            beta[g] = 0.5f * s;
        }
        #pragma unroll
        for (int g = 0; g < Gn; g++) alpha[g] = sigmoidf_(beta[g]);
        #pragma unroll
        for (int g = 0; g < Gn; g++) {
            float s = 0.f;
            #pragma unroll
            for (int g2 = 0; g2 < Gn; g2++) s += alpha[g2] * acc[pidx(g2, g)];
            beta[g] += s;
        }
        if (foc == 0) {
            #pragma unroll
            for (int g = 0; g < Gn; g++)
                smf[ALPo + g * PXT + px] = sigmoidf_(beta[g]);
        }
    }
    __syncthreads();

    // ---------------- final pass: out = sum_g alpha*con + bias ----------------
    {
        const int px  = (t & 31) | ((t >> 7) << 5);   // 0..63
        const int foc = (t >> 5) & 3;                  // 16-fo chunk
        float al[Gn];
        #pragma unroll
        for (int g = 0; g < Gn; g++) al[g] = smf[ALPo + g * PXT + px];

        float* ob = out + (size_t)bi * FOn * HWn + p0;
        #pragma unroll 4
        for (int i = 0; i < 16; i++) {
            int fo = foc * 16 + i;
            float s = 0.f;
            #pragma unroll
            for (int g = 0; g < Gn; g++)
                s += al[g] * smf[CONo + (g * FOn + fo) * SCs + px];
            ob[(size_t)fo * HWn + px] = s + __ldg(&bias[fo]);
        }
    }
}

extern "C" void kernel_launch(void* const* d_in, const int* in_sizes, int n_in,
                              void* d_out, int out_size)
{
    const float* x = nullptr;
    const float* w = nullptr;
    const float* b = nullptr;
    for (int i = 0; i < n_in; i++) {
        if (in_sizes[i] == Bn * Gn * FIn * HWn)      x = (const float*)d_in[i];
        else if (in_sizes[i] == Gn * FOn * FIn)      w = (const float*)d_in[i];
        else if (in_sizes[i] == FOn)                 b = (const float*)d_in[i];
    }
    float* out = (float*)d_out;

    static bool attr_set = false;
    if (!attr_set) {
        cudaFuncSetAttribute(dynrout_mma_kernel,
                             cudaFuncAttributeMaxDynamicSharedMemorySize, SMEM_BYTES);
        attr_set = true;
    }

    const int n_ctas = (Bn * HWn) / PXT;   // 1024
    dynrout_mma_kernel<<<n_ctas, THREADS, SMEM_BYTES>>>(x, w, b, out);
}